// round 16
// baseline (speedup 1.0000x reference)
#include <cuda_runtime.h>
#include <cuda_bf16.h>
#include <cstdint>

#define NN 50000
#define NE 625000
#define NTOT (NN + NE)
#define NPAD 50048              // 391 * 128 (= 782 * 64)

// ---------------- scratch (static device globals; no allocation) ----------------
__device__ float g_bufA[(size_t)NPAD * 128];                 // m (GEMM out), fp32
__device__ __nv_bfloat16 g_AH[(size_t)NPAD * 128];           // A operand hi (x, then h)
__device__ __nv_bfloat16 g_AL[(size_t)NPAD * 128];           // A operand lo
__device__ int   g_deg[NN];
__device__ float g_dinv[NN];
__device__ int   g_rowptr[NN + 1];
__device__ int   g_cursor[NN];
__device__ int   g_srcs[NTOT];
__device__ float g_norms[NTOT];
__device__ int   g_gsums[256];
// transposed, bf16 hi/lo weights: W1t @0, W2t @16384, Wft @32768 (row stride 128)
__device__ __nv_bfloat16 g_WtH[40960];
__device__ __nv_bfloat16 g_WtL[40960];

// ---------------- helpers ----------------
__device__ __forceinline__ uint32_t bfpack(float x, float y) {
    __nv_bfloat162 t;
    t.x = __float2bfloat16(x);
    t.y = __float2bfloat16(y);
    return *reinterpret_cast<uint32_t*>(&t);
}

__device__ __forceinline__ void cp16(uint32_t so, const void* gp) {
    asm volatile("cp.async.cg.shared.global [%0], [%1], 16;\n" :: "r"(so), "l"(gp) : "memory");
}
__device__ __forceinline__ void cp_commit() {
    asm volatile("cp.async.commit_group;\n" ::: "memory");
}
template <int N> __device__ __forceinline__ void cp_wait() {
    asm volatile("cp.async.wait_group %0;\n" :: "n"(N) : "memory");
}

__device__ __forceinline__ void mma16(float* d, const uint32_t* a, const uint32_t* b) {
    asm volatile(
        "mma.sync.aligned.m16n8k16.row.col.f32.bf16.bf16.f32 "
        "{%0,%1,%2,%3}, {%4,%5,%6,%7}, {%8,%9}, {%0,%1,%2,%3};\n"
        : "+f"(d[0]), "+f"(d[1]), "+f"(d[2]), "+f"(d[3])
        : "r"(a[0]), "r"(a[1]), "r"(a[2]), "r"(a[3]), "r"(b[0]), "r"(b[1]));
}

// ---------------- weight prep: transpose + bf16 hi/lo split ----------------
__global__ void k_wprep(const float* __restrict__ W1, const float* __restrict__ W2,
                        const float* __restrict__ Wf) {
    int i = blockIdx.x * 256 + threadIdx.x;
    if (i >= 40960) return;
    const float* W; int off, Nout, j;
    if (i < 16384)      { W = W1; off = 0;     Nout = 128; j = i; }
    else if (i < 32768) { W = W2; off = 16384; Nout = 128; j = i - 16384; }
    else                { W = Wf; off = 32768; Nout = 64;  j = i - 32768; }
    int k = j / Nout, n = j % Nout;
    float v = W[j];
    __nv_bfloat16 h = __float2bfloat16(v);
    float lo = v - __bfloat162float(h);
    g_WtH[off + n * 128 + k] = h;
    g_WtL[off + n * 128 + k] = __float2bfloat16(lo);
}

// ---------------- x prep: fp32 -> bf16 hi/lo, zero-padded to NPAD rows ----------------
__global__ void k_xprep(const float* __restrict__ x) {
    int i = blockIdx.x * 256 + threadIdx.x;      // float4 index, NPAD*32 total
    if (i >= NPAD * 32) return;
    int row = i >> 5;
    float4 v = make_float4(0.f, 0.f, 0.f, 0.f);
    if (row < NN) v = ((const float4*)x)[i];
    float hx = __bfloat162float(__float2bfloat16(v.x));
    float hy = __bfloat162float(__float2bfloat16(v.y));
    float hz = __bfloat162float(__float2bfloat16(v.z));
    float hw = __bfloat162float(__float2bfloat16(v.w));
    uint2 h = make_uint2(bfpack(v.x, v.y), bfpack(v.z, v.w));
    uint2 l = make_uint2(bfpack(v.x - hx, v.y - hy), bfpack(v.z - hz, v.w - hw));
    ((uint2*)g_AH)[i] = h;
    ((uint2*)g_AL)[i] = l;
}

// ---------------- degree / normalization ----------------
__global__ void k_init_deg() {
    int i = blockIdx.x * 256 + threadIdx.x;
    if (i < NN) g_deg[i] = 1;                 // self-loop contributes 1
}

__global__ void k_hist(const int* __restrict__ dst) {
    int e = blockIdx.x * 256 + threadIdx.x;
    if (e < NE) atomicAdd(&g_deg[dst[e]], 1);
}

__global__ void k_scan1() {
    __shared__ int sh[256];
    int t = threadIdx.x;
    int i = blockIdx.x * 256 + t;
    int v = (i < NN) ? g_deg[i] : 0;
    if (i < NN) g_dinv[i] = rsqrtf((float)v);
    sh[t] = v; __syncthreads();
    #pragma unroll
    for (int o = 1; o < 256; o <<= 1) {
        int x = (t >= o) ? sh[t - o] : 0;
        __syncthreads();
        sh[t] += x;
        __syncthreads();
    }
    if (i < NN) g_rowptr[i] = sh[t] - v;
    if (t == 255) g_gsums[blockIdx.x] = sh[255];
}

__global__ void k_scan2(int nb) {
    __shared__ int sh[256];
    int t = threadIdx.x;
    int v = (t < nb) ? g_gsums[t] : 0;
    sh[t] = v; __syncthreads();
    #pragma unroll
    for (int o = 1; o < 256; o <<= 1) {
        int x = (t >= o) ? sh[t - o] : 0;
        __syncthreads();
        sh[t] += x;
        __syncthreads();
    }
    g_gsums[t] = sh[t] - v;
}

__global__ void k_scan3() {
    int i = blockIdx.x * 256 + threadIdx.x;
    if (i < NN) {
        int rp = g_rowptr[i] + g_gsums[i >> 8];
        g_rowptr[i] = rp;
        g_cursor[i] = rp;
    }
    if (i == 0) g_rowptr[NN] = NTOT;
}

// ---------------- bucket fill (CSR by dst) ----------------
__global__ void k_fill_edges(const int* __restrict__ src,
                             const int* __restrict__ dst) {
    int e = blockIdx.x * 256 + threadIdx.x;
    if (e < NE) {
        int s = src[e];
        int d = dst[e];
        int p = atomicAdd(&g_cursor[d], 1);
        g_srcs[p]  = s;
        g_norms[p] = g_dinv[s] * g_dinv[d];
    }
}

__global__ void k_fill_self() {
    int i = blockIdx.x * 256 + threadIdx.x;
    if (i < NN) {
        int p = atomicAdd(&g_cursor[i], 1);
        g_srcs[p] = i;
        float dv = g_dinv[i];
        g_norms[p] = dv * dv;
    }
}

// ---------------- cp.async double-buffered 3x-split BF16 GEMM ----------------
// C[NPAD x BNT] = A * Wt^T; A,Wt pre-split bf16 hi/lo in global [rows][128].
// BM=64 rows per block (split M, not N: A-loads scale WITH the MMAs; B is tiny
// and L2-resident, so duplicating B reads across M-blocks is nearly free).
// Grid 782 @ 3 blocks/SM (444 conc) -> 1.76 waves (88% vs R14's 66%).
// D = ah*bh + ah*bl + al*bh (al*bl ~2^-18, dropped).
template <int BNT>
__global__ void __launch_bounds__(256, 3)
k_gemm_pipe(const __nv_bfloat16* __restrict__ AH, const __nv_bfloat16* __restrict__ AL,
            const __nv_bfloat16* __restrict__ BH, const __nv_bfloat16* __restrict__ BL,
            float* __restrict__ C) {
    constexpr int ASTR = 40, BSTR = 40;       // bf16 elems; bank-conflict-free
    constexpr int ASZ = 64 * ASTR;            // 2560 elems per A buffer
    constexpr int BSZ = BNT * BSTR;           // 5120 or 2560
    constexpr int STG = 2 * ASZ + 2 * BSZ;    // elems per stage (AH,AL,BH,BL)
    constexpr int WN = BNT / 4;               // 32 or 16 cols per warp
    constexpr int NF = WN / 8;                // 4 or 2 n-fragments
    extern __shared__ __nv_bfloat16 sm[];

    const int tid  = threadIdx.x;
    const int lane = tid & 31, wid = tid >> 5;
    const int wm = wid & 1, wn = wid >> 1;    // 2 m-slices x 4 n-slices
    const int row0 = blockIdx.x * 64;
    const int g = lane >> 2, tg = lane & 3;
    const uint32_t sbase = (uint32_t)__cvta_generic_to_shared(sm);

    float acc[2][NF][4];
    #pragma unroll
    for (int i = 0; i < 2; i++)
        #pragma unroll
        for (int j = 0; j < NF; j++)
            #pragma unroll
            for (int q = 0; q < 4; q++) acc[i][j][q] = 0.f;

    auto load_stage = [&](int s, int k0) {
        uint32_t sb = sbase + (uint32_t)(s * STG) * 2;
        // A tile 64x32 bf16 = 256 16B chunks per buffer; 1/thread
        {
            int r = tid >> 2, c16 = tid & 3;
            uint32_t so = sb + (uint32_t)(r * ASTR + c16 * 8) * 2;
            size_t go = (size_t)(row0 + r) * 128 + k0 + c16 * 8;
            cp16(so, AH + go);
            cp16(so + ASZ * 2, AL + go);
        }
        // B tile BNT x 32 bf16 = BNT*4 chunks per buffer; BNT/64 per thread
        #pragma unroll
        for (int l = 0; l < BNT / 64; l++) {
            int id = tid + l * 256;
            int n = id >> 2, c16 = id & 3;
            uint32_t so = sb + (uint32_t)(2 * ASZ + n * BSTR + c16 * 8) * 2;
            size_t go = (size_t)n * 128 + k0 + c16 * 8;
            cp16(so, BH + go);
            cp16(so + BSZ * 2, BL + go);
        }
    };

    load_stage(0, 0);
    cp_commit();

    #pragma unroll
    for (int it = 0; it < 4; it++) {
        if (it < 3) { load_stage((it + 1) & 1, (it + 1) * 32); cp_commit(); }
        if (it < 3) cp_wait<1>(); else cp_wait<0>();
        __syncthreads();

        const __nv_bfloat16* AshH = sm + (it & 1) * STG;
        const __nv_bfloat16* AshL = AshH + ASZ;
        const __nv_bfloat16* BstH = AshH + 2 * ASZ;
        const __nv_bfloat16* BstL = BstH + BSZ;

        #pragma unroll
        for (int ks = 0; ks < 2; ks++) {
            uint32_t ah[2][4], al[2][4];
            #pragma unroll
            for (int mf = 0; mf < 2; mf++) {
                int base = (wm * 32 + mf * 16 + g) * ASTR + ks * 16 + 2 * tg;
                ah[mf][0] = *(const uint32_t*)&AshH[base];
                ah[mf][1] = *(const uint32_t*)&AshH[base + 8 * ASTR];
                ah[mf][2] = *(const uint32_t*)&AshH[base + 8];
                ah[mf][3] = *(const uint32_t*)&AshH[base + 8 * ASTR + 8];
                al[mf][0] = *(const uint32_t*)&AshL[base];
                al[mf][1] = *(const uint32_t*)&AshL[base + 8 * ASTR];
                al[mf][2] = *(const uint32_t*)&AshL[base + 8];
                al[mf][3] = *(const uint32_t*)&AshL[base + 8 * ASTR + 8];
            }
            #pragma unroll
            for (int nf = 0; nf < NF; nf++) {
                int bb = (wn * WN + nf * 8 + g) * BSTR + ks * 16 + 2 * tg;
                uint32_t bh[2], bl[2];
                bh[0] = *(const uint32_t*)&BstH[bb];
                bh[1] = *(const uint32_t*)&BstH[bb + 8];
                bl[0] = *(const uint32_t*)&BstL[bb];
                bl[1] = *(const uint32_t*)&BstL[bb + 8];
                mma16(acc[0][nf], ah[0], bh);
                mma16(acc[1][nf], ah[1], bh);
                mma16(acc[0][nf], ah[0], bl);
                mma16(acc[1][nf], ah[1], bl);
                mma16(acc[0][nf], al[0], bh);
                mma16(acc[1][nf], al[1], bh);
            }
        }
        __syncthreads();
    }

    // store (C is NPAD-row scratch; no masking needed)
    #pragma unroll
    for (int mf = 0; mf < 2; mf++) {
        int r = row0 + wm * 32 + mf * 16 + g;
        #pragma unroll
        for (int nf = 0; nf < NF; nf++) {
            int cc = wn * WN + nf * 8 + tg * 2;
            *(float2*)&C[(size_t)r * BNT + cc] =
                make_float2(acc[mf][nf][0], acc[mf][nf][1]);
            *(float2*)&C[(size_t)(r + 8) * BNT + cc] =
                make_float2(acc[mf][nf][2], acc[mf][nf][3]);
        }
    }
}

// ---------------- aggregation (F=128, relu) writing bf16 hi/lo ----------------
__global__ void k_agg_hl(const float4* __restrict__ m4, const float* __restrict__ bias) {
    constexpr int TPN = 32;
    int node = blockIdx.x * 4 + threadIdx.x / TPN;
    int lane = threadIdx.x % TPN;
    if (node >= NN) return;
    int beg = g_rowptr[node];
    int end = g_rowptr[node + 1];
    float4 acc = make_float4(0.f, 0.f, 0.f, 0.f);

    int e = beg;
    for (; e + 4 <= end; e += 4) {
        int   s0 = g_srcs[e],     s1 = g_srcs[e + 1];
        int   s2 = g_srcs[e + 2], s3 = g_srcs[e + 3];
        float w0 = g_norms[e],     w1 = g_norms[e + 1];
        float w2 = g_norms[e + 2], w3 = g_norms[e + 3];
        float4 v0 = __ldg(&m4[(size_t)s0 * TPN + lane]);
        float4 v1 = __ldg(&m4[(size_t)s1 * TPN + lane]);
        float4 v2 = __ldg(&m4[(size_t)s2 * TPN + lane]);
        float4 v3 = __ldg(&m4[(size_t)s3 * TPN + lane]);
        acc.x += w0 * v0.x + w1 * v1.x + w2 * v2.x + w3 * v3.x;
        acc.y += w0 * v0.y + w1 * v1.y + w2 * v2.y + w3 * v3.y;
        acc.z += w0 * v0.z + w1 * v1.z + w2 * v2.z + w3 * v3.z;
        acc.w += w0 * v0.w + w1 * v1.w + w2 * v2.w + w3 * v3.w;
    }
    for (; e < end; e++) {
        int   s = g_srcs[e];
        float w = g_norms[e];
        float4 v = __ldg(&m4[(size_t)s * TPN + lane]);
        acc.x += w * v.x; acc.y += w * v.y; acc.z += w * v.z; acc.w += w * v.w;
    }

    float4 b = ((const float4*)bias)[lane];
    acc.x = fmaxf(acc.x + b.x, 0.f);
    acc.y = fmaxf(acc.y + b.y, 0.f);
    acc.z = fmaxf(acc.z + b.z, 0.f);
    acc.w = fmaxf(acc.w + b.w, 0.f);

    float hx = __bfloat162float(__float2bfloat16(acc.x));
    float hy = __bfloat162float(__float2bfloat16(acc.y));
    float hz = __bfloat162float(__float2bfloat16(acc.z));
    float hw = __bfloat162float(__float2bfloat16(acc.w));
    uint2 h = make_uint2(bfpack(acc.x, acc.y), bfpack(acc.z, acc.w));
    uint2 l = make_uint2(bfpack(acc.x - hx, acc.y - hy), bfpack(acc.z - hz, acc.w - hw));
    ((uint2*)g_AH)[(size_t)node * TPN + lane] = h;
    ((uint2*)g_AL)[(size_t)node * TPN + lane] = l;
}

// ---------------- fused layer-3 aggregation + log_softmax (F=64) ----------------
__global__ void k_agg_lsm(const float4* __restrict__ m4, const float* __restrict__ bias,
                          float4* __restrict__ out4) {
    constexpr int TPN = 16;
    int node = blockIdx.x * 8 + threadIdx.x / TPN;
    int lane = threadIdx.x % TPN;
    int beg = g_rowptr[node];
    int end = g_rowptr[node + 1];
    float4 acc = make_float4(0.f, 0.f, 0.f, 0.f);

    int e = beg;
    for (; e + 4 <= end; e += 4) {
        int   s0 = g_srcs[e],     s1 = g_srcs[e + 1];
        int   s2 = g_srcs[e + 2], s3 = g_srcs[e + 3];
        float w0 = g_norms[e],     w1 = g_norms[e + 1];
        float w2 = g_norms[e + 2], w3 = g_norms[e + 3];
        float4 v0 = __ldg(&m4[(size_t)s0 * TPN + lane]);
        float4 v1 = __ldg(&m4[(size_t)s1 * TPN + lane]);
        float4 v2 = __ldg(&m4[(size_t)s2 * TPN + lane]);
        float4 v3 = __ldg(&m4[(size_t)s3 * TPN + lane]);
        acc.x += w0 * v0.x + w1 * v1.x + w2 * v2.x + w3 * v3.x;
        acc.y += w0 * v0.y + w1 * v1.y + w2 * v2.y + w3 * v3.y;
        acc.z += w0 * v0.z + w1 * v1.z + w2 * v2.z + w3 * v3.z;
        acc.w += w0 * v0.w + w1 * v1.w + w2 * v2.w + w3 * v3.w;
    }
    for (; e < end; e++) {
        int   s = g_srcs[e];
        float w = g_norms[e];
        float4 v = __ldg(&m4[(size_t)s * TPN + lane]);
        acc.x += w * v.x; acc.y += w * v.y; acc.z += w * v.z; acc.w += w * v.w;
    }

    float4 b = ((const float4*)bias)[lane];
    acc.x += b.x; acc.y += b.y; acc.z += b.z; acc.w += b.w;

    float mx = fmaxf(fmaxf(acc.x, acc.y), fmaxf(acc.z, acc.w));
    #pragma unroll
    for (int o = 8; o; o >>= 1) mx = fmaxf(mx, __shfl_xor_sync(0xffffffffu, mx, o));
    float s = __expf(acc.x - mx) + __expf(acc.y - mx) +
              __expf(acc.z - mx) + __expf(acc.w - mx);
    #pragma unroll
    for (int o = 8; o; o >>= 1) s += __shfl_xor_sync(0xffffffffu, s, o);
    float lz = mx + __logf(s);
    out4[(size_t)node * TPN + lane] =
        make_float4(acc.x - lz, acc.y - lz, acc.z - lz, acc.w - lz);
}

// ---------------- launch (single stream) ----------------
extern "C" void kernel_launch(void* const* d_in, const int* in_sizes, int n_in,
                              void* d_out, int out_size) {
    const float* x  = (const float*)d_in[0];
    const int*   ei = (const int*)d_in[1];     // int32 (JAX x64 disabled)
    const float* W1 = (const float*)d_in[2];
    const float* b1 = (const float*)d_in[3];
    const float* W2 = (const float*)d_in[4];
    const float* b2 = (const float*)d_in[5];
    const float* Wf = (const float*)d_in[6];
    const float* bf = (const float*)d_in[7];
    float* out = (float*)d_out;

    const int* src = ei;          // edge_index[0]
    const int* dst = ei + NE;     // edge_index[1]

    float *bufA;
    __nv_bfloat16 *aH, *aL, *wtH, *wtL;
    cudaGetSymbolAddress((void**)&bufA, g_bufA);
    cudaGetSymbolAddress((void**)&aH,  g_AH);
    cudaGetSymbolAddress((void**)&aL,  g_AL);
    cudaGetSymbolAddress((void**)&wtH, g_WtH);
    cudaGetSymbolAddress((void**)&wtL, g_WtL);

    // 2-stage dynamic smem: BNT=128 -> 2*(2*2560+2*5120)*2 = 61440 B
    //                       BNT=64  -> 2*(2*2560+2*2560)*2 = 40960 B
    cudaFuncSetAttribute(k_gemm_pipe<128>, cudaFuncAttributeMaxDynamicSharedMemorySize, 61440);
    cudaFuncSetAttribute(k_gemm_pipe<64>,  cudaFuncAttributeMaxDynamicSharedMemorySize, 40960);

    const int nbN = (NN + 255) / 256;
    const int nbE = (NE + 255) / 256;
    const int gb  = NPAD / 64;     // 782

    k_init_deg<<<nbN, 256>>>();
    k_wprep<<<160, 256>>>(W1, W2, Wf);
    k_xprep<<<(NPAD * 32 + 255) / 256, 256>>>(x);
    k_gemm_pipe<128><<<gb, 256, 61440>>>(aH, aL, wtH, wtL, bufA);   // #4 (ncu slot)
    k_hist<<<nbE, 256>>>(dst);
    k_scan1<<<nbN, 256>>>();
    k_scan2<<<1, 256>>>(nbN);
    k_scan3<<<nbN, 256>>>();
    k_fill_edges<<<nbE, 256>>>(src, dst);
    k_fill_self<<<nbN, 256>>>();

    // layer 1 aggregation (writes hi/lo bf16 into g_AH/g_AL)
    k_agg_hl<<<(NN + 3) / 4, 128>>>((const float4*)bufA, b1);
    // layer 2
    k_gemm_pipe<128><<<gb, 256, 61440>>>(aH, aL, wtH + 16384, wtL + 16384, bufA);
    k_agg_hl<<<(NN + 3) / 4, 128>>>((const float4*)bufA, b2);
    // layer 3: GEMM then fused aggregation+log_softmax straight to out
    k_gemm_pipe<64><<<gb, 256, 40960>>>(aH, aL, wtH + 32768, wtL + 32768, bufA);
    k_agg_lsm<<<NN / 8, 128>>>((const float4*)bufA, bf, (float4*)out);
}

// round 17
// speedup vs baseline: 1.1039x; 1.1039x over previous
#include <cuda_runtime.h>
#include <cuda_bf16.h>
#include <cstdint>

#define NN 50000
#define NE 625000
#define NTOT (NN + NE)
#define NPAD 50048              // 391 * 128

// ---------------- scratch (static device globals; no allocation) ----------------
__device__ float g_bufA[(size_t)NPAD * 128];                 // m (GEMM out), fp32
__device__ __nv_bfloat16 g_AH[(size_t)NPAD * 128];           // A operand hi (x, then h)
__device__ __nv_bfloat16 g_AL[(size_t)NPAD * 128];           // A operand lo
__device__ int   g_deg[NN];
__device__ float g_dinv[NN];
__device__ int   g_rowptr[NN + 1];
__device__ int   g_cursor[NN];
__device__ int   g_srcs[NTOT];
__device__ float g_norms[NTOT];
__device__ int   g_gsums[256];
// transposed, bf16 hi/lo weights: W1t @0, W2t @16384, Wft @32768 (row stride 128)
__device__ __nv_bfloat16 g_WtH[40960];
__device__ __nv_bfloat16 g_WtL[40960];

// ---------------- helpers ----------------
__device__ __forceinline__ uint32_t bfpack(float x, float y) {
    __nv_bfloat162 t;
    t.x = __float2bfloat16(x);
    t.y = __float2bfloat16(y);
    return *reinterpret_cast<uint32_t*>(&t);
}

__device__ __forceinline__ void cp16(uint32_t so, const void* gp) {
    asm volatile("cp.async.cg.shared.global [%0], [%1], 16;\n" :: "r"(so), "l"(gp) : "memory");
}
__device__ __forceinline__ void cp_commit() {
    asm volatile("cp.async.commit_group;\n" ::: "memory");
}
template <int N> __device__ __forceinline__ void cp_wait() {
    asm volatile("cp.async.wait_group %0;\n" :: "n"(N) : "memory");
}

__device__ __forceinline__ void mma16(float* d, const uint32_t* a, const uint32_t* b) {
    asm volatile(
        "mma.sync.aligned.m16n8k16.row.col.f32.bf16.bf16.f32 "
        "{%0,%1,%2,%3}, {%4,%5,%6,%7}, {%8,%9}, {%0,%1,%2,%3};\n"
        : "+f"(d[0]), "+f"(d[1]), "+f"(d[2]), "+f"(d[3])
        : "r"(a[0]), "r"(a[1]), "r"(a[2]), "r"(a[3]), "r"(b[0]), "r"(b[1]));
}

// ---------------- weight prep: transpose + bf16 hi/lo split ----------------
__global__ void k_wprep(const float* __restrict__ W1, const float* __restrict__ W2,
                        const float* __restrict__ Wf) {
    int i = blockIdx.x * 256 + threadIdx.x;
    if (i >= 40960) return;
    const float* W; int off, Nout, j;
    if (i < 16384)      { W = W1; off = 0;     Nout = 128; j = i; }
    else if (i < 32768) { W = W2; off = 16384; Nout = 128; j = i - 16384; }
    else                { W = Wf; off = 32768; Nout = 64;  j = i - 32768; }
    int k = j / Nout, n = j % Nout;
    float v = W[j];
    __nv_bfloat16 h = __float2bfloat16(v);
    float lo = v - __bfloat162float(h);
    g_WtH[off + n * 128 + k] = h;
    g_WtL[off + n * 128 + k] = __float2bfloat16(lo);
}

// ---------------- x prep: fp32 -> bf16 hi/lo (padded) + zero g_deg ----------------
__global__ void k_xprep(const float* __restrict__ x) {
    int i = blockIdx.x * 256 + threadIdx.x;      // float4 index, NPAD*32 total
    if (i >= NPAD * 32) return;
    if (i < NN) g_deg[i] = 0;                    // replaces k_init_deg (scan1 adds +1)
    int row = i >> 5;
    float4 v = make_float4(0.f, 0.f, 0.f, 0.f);
    if (row < NN) v = ((const float4*)x)[i];
    float hx = __bfloat162float(__float2bfloat16(v.x));
    float hy = __bfloat162float(__float2bfloat16(v.y));
    float hz = __bfloat162float(__float2bfloat16(v.z));
    float hw = __bfloat162float(__float2bfloat16(v.w));
    uint2 h = make_uint2(bfpack(v.x, v.y), bfpack(v.z, v.w));
    uint2 l = make_uint2(bfpack(v.x - hx, v.y - hy), bfpack(v.z - hz, v.w - hw));
    ((uint2*)g_AH)[i] = h;
    ((uint2*)g_AL)[i] = l;
}

// ---------------- degree / normalization ----------------
__global__ void k_hist(const int* __restrict__ dst) {
    int e = blockIdx.x * 256 + threadIdx.x;
    if (e < NE) atomicAdd(&g_deg[dst[e]], 1);
}

__global__ void k_scan1() {
    __shared__ int sh[256];
    int t = threadIdx.x;
    int i = blockIdx.x * 256 + t;
    int v = (i < NN) ? (g_deg[i] + 1) : 0;      // +1 = self-loop
    if (i < NN) g_dinv[i] = rsqrtf((float)v);
    sh[t] = v; __syncthreads();
    #pragma unroll
    for (int o = 1; o < 256; o <<= 1) {
        int x = (t >= o) ? sh[t - o] : 0;
        __syncthreads();
        sh[t] += x;
        __syncthreads();
    }
    if (i < NN) g_rowptr[i] = sh[t] - v;
    if (t == 255) g_gsums[blockIdx.x] = sh[255];
}

// fused scan2+scan3: each block reduces the exclusive prefix of g_gsums at its
// own index (one scalar), then offsets its 256 rowptr entries.
__global__ void k_scan23(int nb) {
    __shared__ int red[256];
    int t = threadIdx.x;
    int b = blockIdx.x;
    red[t] = (t < b && t < nb) ? g_gsums[t] : 0;
    __syncthreads();
    #pragma unroll
    for (int o = 128; o; o >>= 1) {
        if (t < o) red[t] += red[t + o];
        __syncthreads();
    }
    int s = red[0];
    int i = b * 256 + t;
    if (i < NN) {
        int rp = g_rowptr[i] + s;
        g_rowptr[i] = rp;
        g_cursor[i] = rp;
    }
    if (i == 0) g_rowptr[NN] = NTOT;
}

// ---------------- bucket fill (CSR by dst): edges + self-loops in one pass ----------------
__global__ void k_fill(const int* __restrict__ src, const int* __restrict__ dst) {
    int e = blockIdx.x * 256 + threadIdx.x;
    if (e < NE) {
        int s = src[e];
        int d = dst[e];
        int p = atomicAdd(&g_cursor[d], 1);
        g_srcs[p]  = s;
        g_norms[p] = g_dinv[s] * g_dinv[d];
    } else if (e < NTOT) {
        int i = e - NE;                          // self loop for node i
        int p = atomicAdd(&g_cursor[i], 1);
        g_srcs[p] = i;
        float dv = g_dinv[i];
        g_norms[p] = dv * dv;
    }
}

// ---------------- cp.async double-buffered 3x-split BF16 GEMM (R14 config) ----------------
// C[NPAD x BNT] = A * Wt^T; A,Wt pre-split bf16 hi/lo in global [rows][128].
// BM=128 x BN=BNT tile, 2 blocks/SM — max per-block compute density (R15/R16
// showed smaller tiles regress: sync/issue overhead per MMA dominates).
// D = ah*bh + ah*bl + al*bh (al*bl ~2^-18, dropped).
template <int BNT>
__global__ void __launch_bounds__(256, 2)
k_gemm_pipe(const __nv_bfloat16* __restrict__ AH, const __nv_bfloat16* __restrict__ AL,
            const __nv_bfloat16* __restrict__ BH, const __nv_bfloat16* __restrict__ BL,
            float* __restrict__ C) {
    constexpr int ASTR = 40, BSTR = 40;       // bf16 elems; bank-conflict-free
    constexpr int ASZ = 128 * ASTR;           // 5120 elems per A buffer
    constexpr int BSZ = BNT * BSTR;
    constexpr int STG = 2 * ASZ + 2 * BSZ;    // elems per stage (AH,AL,BH,BL)
    constexpr int WN = BNT / 2;
    constexpr int NF = WN / 8;
    extern __shared__ __nv_bfloat16 sm[];

    const int tid  = threadIdx.x;
    const int lane = tid & 31, wid = tid >> 5;
    const int wm = wid & 3, wn = wid >> 2;
    const int row0 = blockIdx.x * 128;
    const int g = lane >> 2, tg = lane & 3;
    const uint32_t sbase = (uint32_t)__cvta_generic_to_shared(sm);

    float acc[2][NF][4];
    #pragma unroll
    for (int i = 0; i < 2; i++)
        #pragma unroll
        for (int j = 0; j < NF; j++)
            #pragma unroll
            for (int q = 0; q < 4; q++) acc[i][j][q] = 0.f;

    auto load_stage = [&](int s, int k0) {
        uint32_t sb = sbase + (uint32_t)(s * STG) * 2;
        #pragma unroll
        for (int l = 0; l < 2; l++) {
            int id = tid + l * 256;
            int r = id >> 2, c16 = id & 3;
            uint32_t so = sb + (uint32_t)(r * ASTR + c16 * 8) * 2;
            size_t go = (size_t)(row0 + r) * 128 + k0 + c16 * 8;
            cp16(so, AH + go);
            cp16(so + ASZ * 2, AL + go);
        }
        #pragma unroll
        for (int l = 0; l < BNT / 64; l++) {
            int id = tid + l * 256;
            int n = id >> 2, c16 = id & 3;
            uint32_t so = sb + (uint32_t)(2 * ASZ + n * BSTR + c16 * 8) * 2;
            size_t go = (size_t)n * 128 + k0 + c16 * 8;
            cp16(so, BH + go);
            cp16(so + BSZ * 2, BL + go);
        }
    };

    load_stage(0, 0);
    cp_commit();

    #pragma unroll
    for (int it = 0; it < 4; it++) {
        if (it < 3) { load_stage((it + 1) & 1, (it + 1) * 32); cp_commit(); }
        if (it < 3) cp_wait<1>(); else cp_wait<0>();
        __syncthreads();

        const __nv_bfloat16* AshH = sm + (it & 1) * STG;
        const __nv_bfloat16* AshL = AshH + ASZ;
        const __nv_bfloat16* BstH = AshH + 2 * ASZ;
        const __nv_bfloat16* BstL = BstH + BSZ;

        #pragma unroll
        for (int ks = 0; ks < 2; ks++) {
            uint32_t ah[2][4], al[2][4];
            #pragma unroll
            for (int mf = 0; mf < 2; mf++) {
                int base = (wm * 32 + mf * 16 + g) * ASTR + ks * 16 + 2 * tg;
                ah[mf][0] = *(const uint32_t*)&AshH[base];
                ah[mf][1] = *(const uint32_t*)&AshH[base + 8 * ASTR];
                ah[mf][2] = *(const uint32_t*)&AshH[base + 8];
                ah[mf][3] = *(const uint32_t*)&AshH[base + 8 * ASTR + 8];
                al[mf][0] = *(const uint32_t*)&AshL[base];
                al[mf][1] = *(const uint32_t*)&AshL[base + 8 * ASTR];
                al[mf][2] = *(const uint32_t*)&AshL[base + 8];
                al[mf][3] = *(const uint32_t*)&AshL[base + 8 * ASTR + 8];
            }
            #pragma unroll
            for (int nf = 0; nf < NF; nf++) {
                int bb = (wn * WN + nf * 8 + g) * BSTR + ks * 16 + 2 * tg;
                uint32_t bh[2], bl[2];
                bh[0] = *(const uint32_t*)&BstH[bb];
                bh[1] = *(const uint32_t*)&BstH[bb + 8];
                bl[0] = *(const uint32_t*)&BstL[bb];
                bl[1] = *(const uint32_t*)&BstL[bb + 8];
                mma16(acc[0][nf], ah[0], bh);
                mma16(acc[1][nf], ah[1], bh);
                mma16(acc[0][nf], ah[0], bl);
                mma16(acc[1][nf], ah[1], bl);
                mma16(acc[0][nf], al[0], bh);
                mma16(acc[1][nf], al[1], bh);
            }
        }
        __syncthreads();
    }

    #pragma unroll
    for (int mf = 0; mf < 2; mf++) {
        int r = row0 + wm * 32 + mf * 16 + g;
        #pragma unroll
        for (int nf = 0; nf < NF; nf++) {
            int cc = wn * WN + nf * 8 + tg * 2;
            *(float2*)&C[(size_t)r * BNT + cc] =
                make_float2(acc[mf][nf][0], acc[mf][nf][1]);
            *(float2*)&C[(size_t)(r + 8) * BNT + cc] =
                make_float2(acc[mf][nf][2], acc[mf][nf][3]);
        }
    }
}

// ---------------- aggregation (F=128, relu) writing bf16 hi/lo ----------------
__global__ void k_agg_hl(const float4* __restrict__ m4, const float* __restrict__ bias) {
    constexpr int TPN = 32;
    int node = blockIdx.x * 4 + threadIdx.x / TPN;
    int lane = threadIdx.x % TPN;
    if (node >= NN) return;
    int beg = g_rowptr[node];
    int end = g_rowptr[node + 1];
    float4 acc = make_float4(0.f, 0.f, 0.f, 0.f);

    int e = beg;
    for (; e + 4 <= end; e += 4) {
        int   s0 = g_srcs[e],     s1 = g_srcs[e + 1];
        int   s2 = g_srcs[e + 2], s3 = g_srcs[e + 3];
        float w0 = g_norms[e],     w1 = g_norms[e + 1];
        float w2 = g_norms[e + 2], w3 = g_norms[e + 3];
        float4 v0 = __ldg(&m4[(size_t)s0 * TPN + lane]);
        float4 v1 = __ldg(&m4[(size_t)s1 * TPN + lane]);
        float4 v2 = __ldg(&m4[(size_t)s2 * TPN + lane]);
        float4 v3 = __ldg(&m4[(size_t)s3 * TPN + lane]);
        acc.x += w0 * v0.x + w1 * v1.x + w2 * v2.x + w3 * v3.x;
        acc.y += w0 * v0.y + w1 * v1.y + w2 * v2.y + w3 * v3.y;
        acc.z += w0 * v0.z + w1 * v1.z + w2 * v2.z + w3 * v3.z;
        acc.w += w0 * v0.w + w1 * v1.w + w2 * v2.w + w3 * v3.w;
    }
    for (; e < end; e++) {
        int   s = g_srcs[e];
        float w = g_norms[e];
        float4 v = __ldg(&m4[(size_t)s * TPN + lane]);
        acc.x += w * v.x; acc.y += w * v.y; acc.z += w * v.z; acc.w += w * v.w;
    }

    float4 b = ((const float4*)bias)[lane];
    acc.x = fmaxf(acc.x + b.x, 0.f);
    acc.y = fmaxf(acc.y + b.y, 0.f);
    acc.z = fmaxf(acc.z + b.z, 0.f);
    acc.w = fmaxf(acc.w + b.w, 0.f);

    float hx = __bfloat162float(__float2bfloat16(acc.x));
    float hy = __bfloat162float(__float2bfloat16(acc.y));
    float hz = __bfloat162float(__float2bfloat16(acc.z));
    float hw = __bfloat162float(__float2bfloat16(acc.w));
    uint2 h = make_uint2(bfpack(acc.x, acc.y), bfpack(acc.z, acc.w));
    uint2 l = make_uint2(bfpack(acc.x - hx, acc.y - hy), bfpack(acc.z - hz, acc.w - hw));
    ((uint2*)g_AH)[(size_t)node * TPN + lane] = h;
    ((uint2*)g_AL)[(size_t)node * TPN + lane] = l;
}

// ---------------- fused layer-3 aggregation + log_softmax (F=64) ----------------
__global__ void k_agg_lsm(const float4* __restrict__ m4, const float* __restrict__ bias,
                          float4* __restrict__ out4) {
    constexpr int TPN = 16;
    int node = blockIdx.x * 8 + threadIdx.x / TPN;
    int lane = threadIdx.x % TPN;
    int beg = g_rowptr[node];
    int end = g_rowptr[node + 1];
    float4 acc = make_float4(0.f, 0.f, 0.f, 0.f);

    int e = beg;
    for (; e + 4 <= end; e += 4) {
        int   s0 = g_srcs[e],     s1 = g_srcs[e + 1];
        int   s2 = g_srcs[e + 2], s3 = g_srcs[e + 3];
        float w0 = g_norms[e],     w1 = g_norms[e + 1];
        float w2 = g_norms[e + 2], w3 = g_norms[e + 3];
        float4 v0 = __ldg(&m4[(size_t)s0 * TPN + lane]);
        float4 v1 = __ldg(&m4[(size_t)s1 * TPN + lane]);
        float4 v2 = __ldg(&m4[(size_t)s2 * TPN + lane]);
        float4 v3 = __ldg(&m4[(size_t)s3 * TPN + lane]);
        acc.x += w0 * v0.x + w1 * v1.x + w2 * v2.x + w3 * v3.x;
        acc.y += w0 * v0.y + w1 * v1.y + w2 * v2.y + w3 * v3.y;
        acc.z += w0 * v0.z + w1 * v1.z + w2 * v2.z + w3 * v3.z;
        acc.w += w0 * v0.w + w1 * v1.w + w2 * v2.w + w3 * v3.w;
    }
    for (; e < end; e++) {
        int   s = g_srcs[e];
        float w = g_norms[e];
        float4 v = __ldg(&m4[(size_t)s * TPN + lane]);
        acc.x += w * v.x; acc.y += w * v.y; acc.z += w * v.z; acc.w += w * v.w;
    }

    float4 b = ((const float4*)bias)[lane];
    acc.x += b.x; acc.y += b.y; acc.z += b.z; acc.w += b.w;

    float mx = fmaxf(fmaxf(acc.x, acc.y), fmaxf(acc.z, acc.w));
    #pragma unroll
    for (int o = 8; o; o >>= 1) mx = fmaxf(mx, __shfl_xor_sync(0xffffffffu, mx, o));
    float s = __expf(acc.x - mx) + __expf(acc.y - mx) +
              __expf(acc.z - mx) + __expf(acc.w - mx);
    #pragma unroll
    for (int o = 8; o; o >>= 1) s += __shfl_xor_sync(0xffffffffu, s, o);
    float lz = mx + __logf(s);
    out4[(size_t)node * TPN + lane] =
        make_float4(acc.x - lz, acc.y - lz, acc.z - lz, acc.w - lz);
}

// ---------------- launch (single stream; 12 launches) ----------------
extern "C" void kernel_launch(void* const* d_in, const int* in_sizes, int n_in,
                              void* d_out, int out_size) {
    const float* x  = (const float*)d_in[0];
    const int*   ei = (const int*)d_in[1];     // int32 (JAX x64 disabled)
    const float* W1 = (const float*)d_in[2];
    const float* b1 = (const float*)d_in[3];
    const float* W2 = (const float*)d_in[4];
    const float* b2 = (const float*)d_in[5];
    const float* Wf = (const float*)d_in[6];
    const float* bf = (const float*)d_in[7];
    float* out = (float*)d_out;

    const int* src = ei;          // edge_index[0]
    const int* dst = ei + NE;     // edge_index[1]

    float *bufA;
    __nv_bfloat16 *aH, *aL, *wtH, *wtL;
    cudaGetSymbolAddress((void**)&bufA, g_bufA);
    cudaGetSymbolAddress((void**)&aH,  g_AH);
    cudaGetSymbolAddress((void**)&aL,  g_AL);
    cudaGetSymbolAddress((void**)&wtH, g_WtH);
    cudaGetSymbolAddress((void**)&wtL, g_WtL);

    // 2-stage dynamic smem: BNT=128 -> 81920 B; BNT=64 -> 61440 B
    cudaFuncSetAttribute(k_gemm_pipe<128>, cudaFuncAttributeMaxDynamicSharedMemorySize, 81920);
    cudaFuncSetAttribute(k_gemm_pipe<64>,  cudaFuncAttributeMaxDynamicSharedMemorySize, 61440);

    const int nbN = (NN + 255) / 256;   // 196
    const int nbE = (NE + 255) / 256;
    const int gb  = NPAD / 128;    // 391

    k_wprep<<<160, 256>>>(W1, W2, Wf);                              // #1
    k_xprep<<<(NPAD * 32 + 255) / 256, 256>>>(x);                   // #2 (also zeroes deg)
    k_hist<<<nbE, 256>>>(dst);                                      // #3
    k_gemm_pipe<128><<<gb, 256, 81920>>>(aH, aL, wtH, wtL, bufA);   // #4 (ncu slot)
    k_scan1<<<nbN, 256>>>();                                        // #5
    k_scan23<<<nbN, 256>>>(nbN);                                    // #6
    k_fill<<<(NTOT + 255) / 256, 256>>>(src, dst);                  // #7
    k_agg_hl<<<(NN + 3) / 4, 128>>>((const float4*)bufA, b1);       // #8
    k_gemm_pipe<128><<<gb, 256, 81920>>>(aH, aL, wtH + 16384, wtL + 16384, bufA);
    k_agg_hl<<<(NN + 3) / 4, 128>>>((const float4*)bufA, b2);
    k_gemm_pipe<64><<<gb, 256, 61440>>>(aH, aL, wtH + 32768, wtL + 32768, bufA);
    k_agg_lsm<<<NN / 8, 128>>>((const float4*)bufA, bf, (float4*)out);
}